// round 14
// baseline (speedup 1.0000x reference)
#include <cuda_runtime.h>
#include <cuda_fp16.h>
#include <math.h>

#define NB 4
#define DD 16
#define HH 512
#define WW 512
#define PLANE (HH*WW)
#define VOL (DD*PLANE)
#define TOT (NB*VOL)
#define C1F 0.0001f
#define C2F 0.0009f

// Gaussian weights (sigma=1.5, wsize=11) as literals -> FFMA-imm (rt_SMSP=1).
#define GW0 0.00102838f
#define GW1 0.00759875f
#define GW2 0.03600077f
#define GW3 0.10936069f
#define GW4 0.21300554f
#define GW5 0.26601173f

// Blurred fields, fp16 STORAGE ONLY (fp32 arithmetic everywhere — fp16
// accumulation breaks the variance cancellation, proven R11). A=p+g, B=p-g.
__device__ __half2 gAB[TOT];   // ( blur(A),   blur(B)   )
__device__ __half2 gSQ[TOT];   // ( blur(A^2), blur(B^2) )
// [0..3] per-n sum (p-g)^2 ; [4..7] per-n sum ssim_map. Zero at load; the
// fused finalizer re-zeroes after reading so each replay starts clean.
__device__ double g_acc[8];
__device__ unsigned int g_cnt;   // zero-init; reset by finalizer

__device__ __forceinline__ float blur11(const float* v) {
    float a;
    a = v[0]  * GW0;
    a = fmaf(v[1],  GW1, a);
    a = fmaf(v[2],  GW2, a);
    a = fmaf(v[3],  GW3, a);
    a = fmaf(v[4],  GW4, a);
    a = fmaf(v[5],  GW5, a);
    a = fmaf(v[6],  GW4, a);
    a = fmaf(v[7],  GW3, a);
    a = fmaf(v[8],  GW2, a);
    a = fmaf(v[9],  GW1, a);
    a = fmaf(v[10], GW0, a);
    return a;
}

// Fused field-gen + W-blur + H-blur per (n,d) slice tile; PSNR fused.
// EXACT R10 interior (proven best: regs 32, occ 96%); grid restricted to one
// n per launch so ssim_d(n) reads these outputs from L2.
__global__ __launch_bounds__(256) void blur2d_kernel(
    const float* __restrict__ pred, const float* __restrict__ gt, int n)
{
    __shared__ float sA[42][45];   // A = p+g (stride 45: conflict-free W reads)
    __shared__ float sB[42][45];   // B = p-g
    __shared__ float tx[42][33];   // tmp (stride 33 -> conflict-free STS/LDS)
    __shared__ float ty[42][33];
    __shared__ float red[256];

    int z = n * DD + blockIdx.z;          // blockIdx.z = d (0..15)
    const float* pz = pred + (size_t)z * PLANE;
    const float* gz = gt   + (size_t)z * PLANE;
    int h0 = blockIdx.y * 32 - 5;
    int w0 = blockIdx.x * 32 - 5;
    int hb = blockIdx.y * 32, wb = blockIdx.x * 32;
    int tid = threadIdx.x;

    // ---- Load 42x42 tile (clamped = replicate pad), basis transform ----
    for (int i = tid; i < 42*42; i += 256) {
        int r = i / 42, c = i - r*42;
        int hh = min(max(h0 + r, 0), HH-1);
        int ww = min(max(w0 + c, 0), WW-1);
        float p = pz[hh*WW + ww];
        float g = gz[hh*WW + ww];
        sA[r][c] = p + g;
        sB[r][c] = p - g;
    }
    __syncthreads();

    // ---- PSNR partial over interior 32x32: (p-g)^2 = B^2 ----
    float psum = 0.f;
    #pragma unroll
    for (int i = 0; i < 4; i++) {
        int j = tid + i*256;
        int r = 5 + (j >> 5), c = 5 + (j & 31);
        float d = sB[r][c];
        psum = fmaf(d, d, psum);
    }

    int rW = tid >> 2, chW = (tid & 3) * 8;   // W-pass coords (tid < 168)
    int hch = tid >> 5, cH = tid & 31;        // H-pass coords (tid < 128)

    // ======== Pass 1: {A, B} ========
    if (tid < 168) {
        float vx[18], vy[18];
        #pragma unroll
        for (int k = 0; k < 18; k++) { vx[k] = sA[rW][chW + k]; vy[k] = sB[rW][chW + k]; }
        #pragma unroll
        for (int o = 0; o < 8; o++) {
            tx[rW][chW + o] = blur11(vx + o);
            ty[rW][chW + o] = blur11(vy + o);
        }
    }
    __syncthreads();
    if (tid < 128) {
        float vx[18], vy[18];
        #pragma unroll
        for (int k = 0; k < 18; k++) { vx[k] = tx[hch*8 + k][cH]; vy[k] = ty[hch*8 + k][cH]; }
        __half2* oAB = &gAB[(size_t)z * PLANE];
        #pragma unroll
        for (int o = 0; o < 8; o++) {
            int row = hb + hch*8 + o;
            oAB[row*WW + wb + cH] = __floats2half2_rn(blur11(vx + o), blur11(vy + o));
        }
    }
    __syncthreads();

    // ======== Pass 2: {A^2, B^2} (squared on load) ========
    if (tid < 168) {
        float vx[18], vy[18];
        #pragma unroll
        for (int k = 0; k < 18; k++) {
            float a = sA[rW][chW + k], b = sB[rW][chW + k];
            vx[k] = a * a; vy[k] = b * b;
        }
        #pragma unroll
        for (int o = 0; o < 8; o++) {
            tx[rW][chW + o] = blur11(vx + o);
            ty[rW][chW + o] = blur11(vy + o);
        }
    }
    __syncthreads();
    if (tid < 128) {
        float vx[18], vy[18];
        #pragma unroll
        for (int k = 0; k < 18; k++) { vx[k] = tx[hch*8 + k][cH]; vy[k] = ty[hch*8 + k][cH]; }
        __half2* oSQ = &gSQ[(size_t)z * PLANE];
        #pragma unroll
        for (int o = 0; o < 8; o++) {
            int row = hb + hch*8 + o;
            oSQ[row*WW + wb + cH] = __floats2half2_rn(blur11(vx + o), blur11(vy + o));
        }
    }
    __syncthreads();

    // ---- PSNR block reduce ----
    red[tid] = psum;
    __syncthreads();
    #pragma unroll
    for (int s = 128; s > 0; s >>= 1) {
        if (tid < s) red[tid] += red[tid + s];
        __syncthreads();
    }
    if (tid == 0) atomicAdd(&g_acc[n], (double)red[0]);
}

#define SSIM_BLOCKS (NB * (PLANE/256))   // total across all 4 per-n launches

// D-blur in fp32 registers (D=16, clamped), 4 fields, + SSIM + reduction.
// Grid = PLANE/256 blocks for ONE n; inputs are L2-warm from blur2d(n).
// Finalizer fires in the globally-last block (counter spans all launches).
__global__ __launch_bounds__(256) void ssim_d_kernel(float* out, int out_size, int n) {
    int tid = threadIdx.x;
    int idx = blockIdx.x * 256 + tid;
    size_t base = (size_t)n * VOL + idx;

    float iA[16], iB[16], iA2[16], iB2[16];
    #pragma unroll
    for (int d = 0; d < 16; d++) {
        size_t off = base + (size_t)d * PLANE;
        float2 a = __half22float2(gAB[off]);
        float2 b = __half22float2(gSQ[off]);
        iA[d]  = a.x; iB[d]  = a.y;
        iA2[d] = b.x; iB2[d] = b.y;
    }

    const float wq[11] = {GW0,GW1,GW2,GW3,GW4,GW5,GW4,GW3,GW2,GW1,GW0};
    float ssum = 0.f;
    #pragma unroll
    for (int d = 0; d < 16; d++) {
        float mA=0.f, mB=0.f, eA=0.f, eB=0.f;
        #pragma unroll
        for (int k = 0; k < 11; k++) {
            int dd = d - 5 + k;
            dd = dd < 0 ? 0 : (dd > 15 ? 15 : dd);   // compile-time after unroll
            float w = wq[k];                          // literal after unroll
            mA = fmaf(iA[dd],  w, mA);
            mB = fmaf(iB[dd],  w, mB);
            eA = fmaf(iA2[dd], w, eA);
            eB = fmaf(iB2[dd], w, eB);
        }
        float mA2 = mA*mA, mB2 = mB*mB;
        float mu12 = 0.25f * (mA2 - mB2);       // mu1*mu2
        float musq = 0.5f  * (mA2 + mB2);       // mu1^2 + mu2^2
        float Epg  = 0.25f * (eA - eB);         // E[p*g]
        float Esq  = 0.5f  * (eA + eB);         // E[p^2] + E[g^2]
        float s12  = Epg - mu12;
        float s1s2 = Esq - musq;
        float v1 = 2.f*s12 + C2F;
        float v2 = s1s2 + C2F;
        float num = (2.f*mu12 + C1F) * v1;
        float den = (musq + C1F) * v2;
        ssum += __fdividef(num, den);
    }

    __shared__ float red[256];
    red[tid] = ssum;
    __syncthreads();
    #pragma unroll
    for (int s = 128; s > 0; s >>= 1) {
        if (tid < s) red[tid] += red[tid + s];
        __syncthreads();
    }
    if (tid == 0) {
        atomicAdd(&g_acc[4 + n], (double)red[0]);
        __threadfence();
        unsigned int done = atomicAdd(&g_cnt, 1u);
        if (done == SSIM_BLOCKS - 1) {
            float psnr = 0.f, ssim = 0.f;
            #pragma unroll
            for (int k = 0; k < NB; k++) {
                float mse = (float)(g_acc[k] / (double)VOL);
                psnr += 10.0f * log10f(1.0f / mse);
                ssim += (float)(g_acc[4 + k] / (double)VOL);
            }
            if (out_size > 0) out[0] = psnr;
            if (out_size > 1) out[1] = ssim;
            if (out_size > 2) out[2] = (float)NB;
            for (int i = 3; i < out_size; i++) out[i] = 0.f;
            for (int i = 0; i < 8; i++) g_acc[i] = 0.0;  // restore invariant
            g_cnt = 0u;
        }
    }
}

extern "C" void kernel_launch(void* const* d_in, const int* in_sizes, int n_in,
                              void* d_out, int out_size) {
    const float* pred = (const float*)d_in[0];
    const float* gt   = (const float*)d_in[1];

    dim3 g1(WW/32, HH/32, DD);      // one n per launch
    dim3 g2(PLANE/256);

    // Interleave per-n: ssim_d(n) runs right after blur2d(n), while the
    // 33.5MB of per-n intermediates are still resident in the 126MB L2.
    for (int n = 0; n < NB; n++) {
        blur2d_kernel<<<g1, 256>>>(pred, gt, n);
        ssim_d_kernel<<<g2, 256>>>((float*)d_out, out_size, n);
    }
}

// round 15
// speedup vs baseline: 1.1111x; 1.1111x over previous
#include <cuda_runtime.h>
#include <cuda_fp16.h>
#include <math.h>

#define NB 4
#define DD 16
#define HH 512
#define WW 512
#define PLANE (HH*WW)
#define VOL (DD*PLANE)
#define TOT (NB*VOL)
#define C1F 0.0001f
#define C2F 0.0009f

// Gaussian weights (sigma=1.5, wsize=11) as literals -> FFMA-imm (rt_SMSP=1).
#define GW0 0.00102838f
#define GW1 0.00759875f
#define GW2 0.03600077f
#define GW3 0.10936069f
#define GW4 0.21300554f
#define GW5 0.26601173f

// Blurred fields, fp16 STORAGE ONLY (fp32 arithmetic everywhere — fp16
// accumulation breaks the variance cancellation, proven R11). A=p+g, B=p-g.
__device__ __half2 gAB[TOT];   // ( blur(A),   blur(B)   )
__device__ __half2 gSQ[TOT];   // ( blur(A^2), blur(B^2) )
// [0..3] per-n sum (p-g)^2 ; [4..7] per-n sum ssim_map. Zero at load; the
// fused finalizer re-zeroes after reading so each replay starts clean.
__device__ double g_acc[8];
__device__ unsigned int g_cnt;   // zero-init; reset by finalizer

__device__ __forceinline__ float blur11(const float* v) {
    float a;
    a = v[0]  * GW0;
    a = fmaf(v[1],  GW1, a);
    a = fmaf(v[2],  GW2, a);
    a = fmaf(v[3],  GW3, a);
    a = fmaf(v[4],  GW4, a);
    a = fmaf(v[5],  GW5, a);
    a = fmaf(v[6],  GW4, a);
    a = fmaf(v[7],  GW3, a);
    a = fmaf(v[8],  GW2, a);
    a = fmaf(v[9],  GW1, a);
    a = fmaf(v[10], GW0, a);
    return a;
}

// Fused field-gen + W-blur + H-blur per (n,d) slice tile; PSNR fused into the
// load loop. R10's proven W/H phases untouched. Inputs read with __ldcs
// (evict-first) so the 256MB input stream doesn't flush the intermediates
// out of L2 before ssim_d reads them.
__global__ __launch_bounds__(256) void blur2d_kernel(
    const float* __restrict__ pred, const float* __restrict__ gt)
{
    __shared__ float sA[42][45];   // A = p+g (stride 45: conflict-free W reads)
    __shared__ float sB[42][45];   // B = p-g
    __shared__ float tx[42][33];   // tmp (stride 33 -> conflict-free STS/LDS)
    __shared__ float ty[42][33];
    __shared__ float red[256];

    int z = blockIdx.z;
    int n = z >> 4;
    const float* pz = pred + (size_t)z * PLANE;
    const float* gz = gt   + (size_t)z * PLANE;
    int h0 = blockIdx.y * 32 - 5;
    int w0 = blockIdx.x * 32 - 5;
    int hb = blockIdx.y * 32, wb = blockIdx.x * 32;
    int tid = threadIdx.x;

    // ---- Load 42x42 tile (clamped = replicate pad) + fused PSNR partial ----
    float psum = 0.f;
    bool interior = (h0 >= 0) & (w0 >= 0) & (h0 + 42 <= HH) & (w0 + 42 <= WW);
    if (interior) {
        const float* pb = pz + h0*WW + w0;
        const float* gb = gz + h0*WW + w0;
        for (int i = tid; i < 42*42; i += 256) {
            int r = i / 42, c = i - r*42;
            float p = __ldcs(pb + r*WW + c);
            float g = __ldcs(gb + r*WW + c);
            float A = p + g, B = p - g;
            sA[r][c] = A; sB[r][c] = B;
            if (r >= 5 && r < 37 && c >= 5 && c < 37) psum = fmaf(B, B, psum);
        }
    } else {
        for (int i = tid; i < 42*42; i += 256) {
            int r = i / 42, c = i - r*42;
            int hh = min(max(h0 + r, 0), HH-1);
            int ww = min(max(w0 + c, 0), WW-1);
            float p = __ldcs(pz + hh*WW + ww);
            float g = __ldcs(gz + hh*WW + ww);
            float A = p + g, B = p - g;
            sA[r][c] = A; sB[r][c] = B;
            if (r >= 5 && r < 37 && c >= 5 && c < 37) psum = fmaf(B, B, psum);
        }
    }
    __syncthreads();

    int rW = tid >> 2, chW = (tid & 3) * 8;   // W-pass coords (tid < 168)
    int hch = tid >> 5, cH = tid & 31;        // H-pass coords (tid < 128)

    // ======== Pass 1: {A, B} ========
    if (tid < 168) {
        float vx[18], vy[18];
        #pragma unroll
        for (int k = 0; k < 18; k++) { vx[k] = sA[rW][chW + k]; vy[k] = sB[rW][chW + k]; }
        #pragma unroll
        for (int o = 0; o < 8; o++) {
            tx[rW][chW + o] = blur11(vx + o);
            ty[rW][chW + o] = blur11(vy + o);
        }
    }
    __syncthreads();
    if (tid < 128) {
        float vx[18], vy[18];
        #pragma unroll
        for (int k = 0; k < 18; k++) { vx[k] = tx[hch*8 + k][cH]; vy[k] = ty[hch*8 + k][cH]; }
        __half2* oAB = &gAB[(size_t)z * PLANE];
        #pragma unroll
        for (int o = 0; o < 8; o++) {
            int row = hb + hch*8 + o;
            oAB[row*WW + wb + cH] = __floats2half2_rn(blur11(vx + o), blur11(vy + o));
        }
    }
    __syncthreads();

    // ======== Pass 2: {A^2, B^2} (squared on load) ========
    if (tid < 168) {
        float vx[18], vy[18];
        #pragma unroll
        for (int k = 0; k < 18; k++) {
            float a = sA[rW][chW + k], b = sB[rW][chW + k];
            vx[k] = a * a; vy[k] = b * b;
        }
        #pragma unroll
        for (int o = 0; o < 8; o++) {
            tx[rW][chW + o] = blur11(vx + o);
            ty[rW][chW + o] = blur11(vy + o);
        }
    }
    __syncthreads();
    if (tid < 128) {
        float vx[18], vy[18];
        #pragma unroll
        for (int k = 0; k < 18; k++) { vx[k] = tx[hch*8 + k][cH]; vy[k] = ty[hch*8 + k][cH]; }
        __half2* oSQ = &gSQ[(size_t)z * PLANE];
        #pragma unroll
        for (int o = 0; o < 8; o++) {
            int row = hb + hch*8 + o;
            oSQ[row*WW + wb + cH] = __floats2half2_rn(blur11(vx + o), blur11(vy + o));
        }
    }
    __syncthreads();

    // ---- PSNR block reduce ----
    red[tid] = psum;
    __syncthreads();
    #pragma unroll
    for (int s = 128; s > 0; s >>= 1) {
        if (tid < s) red[tid] += red[tid + s];
        __syncthreads();
    }
    if (tid == 0) atomicAdd(&g_acc[n], (double)red[0]);
}

#define SSIM_BLOCKS (NB * (PLANE/256))

// D-blur in fp32 registers (D=16, clamped), 4 fields, + SSIM + reduction,
// finalizer fused into the last block. Block->data mapping is REVERSED so the
// first waves read the intermediates blur2d wrote LAST (still L2-resident);
// __ldcs keeps these read-once loads from polluting L2 further.
__global__ __launch_bounds__(256) void ssim_d_kernel(float* out, int out_size) {
    int tid = threadIdx.x;
    // Reverse mapping: highest (n, idx) processed by the earliest blocks.
    int n   = (NB - 1) - blockIdx.y;
    int bx  = (gridDim.x - 1) - blockIdx.x;
    int idx = bx * 256 + tid;
    size_t base = (size_t)n * VOL + idx;

    float iA[16], iB[16], iA2[16], iB2[16];
    #pragma unroll
    for (int d = 0; d < 16; d++) {
        size_t off = base + (size_t)d * PLANE;
        float2 a = __half22float2(__ldcs(&gAB[off]));
        float2 b = __half22float2(__ldcs(&gSQ[off]));
        iA[d]  = a.x; iB[d]  = a.y;
        iA2[d] = b.x; iB2[d] = b.y;
    }

    const float wq[11] = {GW0,GW1,GW2,GW3,GW4,GW5,GW4,GW3,GW2,GW1,GW0};
    float ssum = 0.f;
    #pragma unroll
    for (int d = 0; d < 16; d++) {
        float mA=0.f, mB=0.f, eA=0.f, eB=0.f;
        #pragma unroll
        for (int k = 0; k < 11; k++) {
            int dd = d - 5 + k;
            dd = dd < 0 ? 0 : (dd > 15 ? 15 : dd);   // compile-time after unroll
            float w = wq[k];                          // literal after unroll
            mA = fmaf(iA[dd],  w, mA);
            mB = fmaf(iB[dd],  w, mB);
            eA = fmaf(iA2[dd], w, eA);
            eB = fmaf(iB2[dd], w, eB);
        }
        float mA2 = mA*mA, mB2 = mB*mB;
        float mu12 = 0.25f * (mA2 - mB2);       // mu1*mu2
        float musq = 0.5f  * (mA2 + mB2);       // mu1^2 + mu2^2
        float Epg  = 0.25f * (eA - eB);         // E[p*g]
        float Esq  = 0.5f  * (eA + eB);         // E[p^2] + E[g^2]
        float s12  = Epg - mu12;
        float s1s2 = Esq - musq;
        float v1 = 2.f*s12 + C2F;
        float v2 = s1s2 + C2F;
        float num = (2.f*mu12 + C1F) * v1;
        float den = (musq + C1F) * v2;
        ssum += __fdividef(num, den);
    }

    __shared__ float red[256];
    red[tid] = ssum;
    __syncthreads();
    #pragma unroll
    for (int s = 128; s > 0; s >>= 1) {
        if (tid < s) red[tid] += red[tid + s];
        __syncthreads();
    }
    if (tid == 0) {
        atomicAdd(&g_acc[4 + n], (double)red[0]);
        __threadfence();
        unsigned int done = atomicAdd(&g_cnt, 1u);
        if (done == SSIM_BLOCKS - 1) {
            float psnr = 0.f, ssim = 0.f;
            #pragma unroll
            for (int k = 0; k < NB; k++) {
                float mse = (float)(g_acc[k] / (double)VOL);
                psnr += 10.0f * log10f(1.0f / mse);
                ssim += (float)(g_acc[4 + k] / (double)VOL);
            }
            if (out_size > 0) out[0] = psnr;
            if (out_size > 1) out[1] = ssim;
            if (out_size > 2) out[2] = (float)NB;
            for (int i = 3; i < out_size; i++) out[i] = 0.f;
            for (int i = 0; i < 8; i++) g_acc[i] = 0.0;  // restore invariant
            g_cnt = 0u;
        }
    }
}

extern "C" void kernel_launch(void* const* d_in, const int* in_sizes, int n_in,
                              void* d_out, int out_size) {
    const float* pred = (const float*)d_in[0];
    const float* gt   = (const float*)d_in[1];

    dim3 g1(WW/32, HH/32, NB*DD);
    blur2d_kernel<<<g1, 256>>>(pred, gt);

    dim3 g2(PLANE/256, NB);
    ssim_d_kernel<<<g2, 256>>>((float*)d_out, out_size);
}

// round 16
// speedup vs baseline: 1.1357x; 1.0222x over previous
#include <cuda_runtime.h>
#include <cuda_fp16.h>
#include <math.h>

#define NB 4
#define DD 16
#define HH 512
#define WW 512
#define PLANE (HH*WW)
#define VOL (DD*PLANE)
#define TOT (NB*VOL)
#define C1F 0.0001f
#define C2F 0.0009f

// Gaussian weights (sigma=1.5, wsize=11) as literals -> FFMA-imm (rt_SMSP=1).
#define GW0 0.00102838f
#define GW1 0.00759875f
#define GW2 0.03600077f
#define GW3 0.10936069f
#define GW4 0.21300554f
#define GW5 0.26601173f

// Blurred fields, fp16 STORAGE ONLY (fp32 arithmetic everywhere — fp16
// accumulation breaks the variance cancellation, proven R11). A=p+g, B=p-g.
__device__ __half2 gAB[TOT];   // ( blur(A),   blur(B)   )
__device__ __half2 gSQ[TOT];   // ( blur(A^2), blur(B^2) )
// [0..3] per-n sum (p-g)^2 ; [4..7] per-n sum ssim_map. Zero at load; the
// fused finalizer re-zeroes after reading so each replay starts clean.
__device__ double g_acc[8];
__device__ unsigned int g_cnt;   // zero-init; reset by finalizer

__device__ __forceinline__ float blur11(const float* v) {
    float a;
    a = v[0]  * GW0;
    a = fmaf(v[1],  GW1, a);
    a = fmaf(v[2],  GW2, a);
    a = fmaf(v[3],  GW3, a);
    a = fmaf(v[4],  GW4, a);
    a = fmaf(v[5],  GW5, a);
    a = fmaf(v[6],  GW4, a);
    a = fmaf(v[7],  GW3, a);
    a = fmaf(v[8],  GW2, a);
    a = fmaf(v[9],  GW1, a);
    a = fmaf(v[10], GW0, a);
    return a;
}

// Fused field-gen + W-blur + H-blur per (n,d) slice tile; PSNR fused.
// EXACT R10 interior (proven best: regs 32, occ 96%, ~134us).
__global__ __launch_bounds__(256) void blur2d_kernel(
    const float* __restrict__ pred, const float* __restrict__ gt)
{
    __shared__ float sA[42][45];   // A = p+g (stride 45: conflict-free W reads)
    __shared__ float sB[42][45];   // B = p-g
    __shared__ float tx[42][33];   // tmp (stride 33 -> conflict-free STS/LDS)
    __shared__ float ty[42][33];
    __shared__ float red[256];

    int z = blockIdx.z;
    int n = z >> 4;
    const float* pz = pred + (size_t)z * PLANE;
    const float* gz = gt   + (size_t)z * PLANE;
    int h0 = blockIdx.y * 32 - 5;
    int w0 = blockIdx.x * 32 - 5;
    int hb = blockIdx.y * 32, wb = blockIdx.x * 32;
    int tid = threadIdx.x;

    // ---- Load 42x42 tile (clamped = replicate pad), basis transform ----
    for (int i = tid; i < 42*42; i += 256) {
        int r = i / 42, c = i - r*42;
        int hh = min(max(h0 + r, 0), HH-1);
        int ww = min(max(w0 + c, 0), WW-1);
        float p = pz[hh*WW + ww];
        float g = gz[hh*WW + ww];
        sA[r][c] = p + g;
        sB[r][c] = p - g;
    }
    __syncthreads();

    // ---- PSNR partial over interior 32x32: (p-g)^2 = B^2 ----
    float psum = 0.f;
    #pragma unroll
    for (int i = 0; i < 4; i++) {
        int j = tid + i*256;
        int r = 5 + (j >> 5), c = 5 + (j & 31);
        float d = sB[r][c];
        psum = fmaf(d, d, psum);
    }

    int rW = tid >> 2, chW = (tid & 3) * 8;   // W-pass coords (tid < 168)
    int hch = tid >> 5, cH = tid & 31;        // H-pass coords (tid < 128)

    // ======== Pass 1: {A, B} ========
    if (tid < 168) {
        float vx[18], vy[18];
        #pragma unroll
        for (int k = 0; k < 18; k++) { vx[k] = sA[rW][chW + k]; vy[k] = sB[rW][chW + k]; }
        #pragma unroll
        for (int o = 0; o < 8; o++) {
            tx[rW][chW + o] = blur11(vx + o);
            ty[rW][chW + o] = blur11(vy + o);
        }
    }
    __syncthreads();
    if (tid < 128) {
        float vx[18], vy[18];
        #pragma unroll
        for (int k = 0; k < 18; k++) { vx[k] = tx[hch*8 + k][cH]; vy[k] = ty[hch*8 + k][cH]; }
        __half2* oAB = &gAB[(size_t)z * PLANE];
        #pragma unroll
        for (int o = 0; o < 8; o++) {
            int row = hb + hch*8 + o;
            oAB[row*WW + wb + cH] = __floats2half2_rn(blur11(vx + o), blur11(vy + o));
        }
    }
    __syncthreads();

    // ======== Pass 2: {A^2, B^2} (squared on load) ========
    if (tid < 168) {
        float vx[18], vy[18];
        #pragma unroll
        for (int k = 0; k < 18; k++) {
            float a = sA[rW][chW + k], b = sB[rW][chW + k];
            vx[k] = a * a; vy[k] = b * b;
        }
        #pragma unroll
        for (int o = 0; o < 8; o++) {
            tx[rW][chW + o] = blur11(vx + o);
            ty[rW][chW + o] = blur11(vy + o);
        }
    }
    __syncthreads();
    if (tid < 128) {
        float vx[18], vy[18];
        #pragma unroll
        for (int k = 0; k < 18; k++) { vx[k] = tx[hch*8 + k][cH]; vy[k] = ty[hch*8 + k][cH]; }
        __half2* oSQ = &gSQ[(size_t)z * PLANE];
        #pragma unroll
        for (int o = 0; o < 8; o++) {
            int row = hb + hch*8 + o;
            oSQ[row*WW + wb + cH] = __floats2half2_rn(blur11(vx + o), blur11(vy + o));
        }
    }
    __syncthreads();

    // ---- PSNR block reduce ----
    red[tid] = psum;
    __syncthreads();
    #pragma unroll
    for (int s = 128; s > 0; s >>= 1) {
        if (tid < s) red[tid] += red[tid + s];
        __syncthreads();
    }
    if (tid == 0) atomicAdd(&g_acc[n], (double)red[0]);
}

#define SSIM_BLOCKS (NB * (PLANE/256))

// D-blur in fp32 registers (D=16, clamped), 4 fields, + SSIM + reduction,
// finalizer fused into the last block. R10 math exactly; the ONLY change is
// __launch_bounds__(256, 5): cap regs at 51 so 5 blocks/SM fit (occ 42->53%).
// The d-loop's live window is in[d-5..d+5] (44 floats), so a <=51-reg
// schedule exists without meaningful spilling.
__global__ __launch_bounds__(256, 5) void ssim_d_kernel(float* out, int out_size) {
    int tid = threadIdx.x;
    int idx = blockIdx.x * 256 + tid;
    int n   = blockIdx.y;
    size_t base = (size_t)n * VOL + idx;

    float iA[16], iB[16], iA2[16], iB2[16];
    #pragma unroll
    for (int d = 0; d < 16; d++) {
        size_t off = base + (size_t)d * PLANE;
        float2 a = __half22float2(gAB[off]);
        float2 b = __half22float2(gSQ[off]);
        iA[d]  = a.x; iB[d]  = a.y;
        iA2[d] = b.x; iB2[d] = b.y;
    }

    const float wq[11] = {GW0,GW1,GW2,GW3,GW4,GW5,GW4,GW3,GW2,GW1,GW0};
    float ssum = 0.f;
    #pragma unroll
    for (int d = 0; d < 16; d++) {
        float mA=0.f, mB=0.f, eA=0.f, eB=0.f;
        #pragma unroll
        for (int k = 0; k < 11; k++) {
            int dd = d - 5 + k;
            dd = dd < 0 ? 0 : (dd > 15 ? 15 : dd);   // compile-time after unroll
            float w = wq[k];                          // literal after unroll
            mA = fmaf(iA[dd],  w, mA);
            mB = fmaf(iB[dd],  w, mB);
            eA = fmaf(iA2[dd], w, eA);
            eB = fmaf(iB2[dd], w, eB);
        }
        float mA2 = mA*mA, mB2 = mB*mB;
        float mu12 = 0.25f * (mA2 - mB2);       // mu1*mu2
        float musq = 0.5f  * (mA2 + mB2);       // mu1^2 + mu2^2
        float Epg  = 0.25f * (eA - eB);         // E[p*g]
        float Esq  = 0.5f  * (eA + eB);         // E[p^2] + E[g^2]
        float s12  = Epg - mu12;
        float s1s2 = Esq - musq;
        float v1 = 2.f*s12 + C2F;
        float v2 = s1s2 + C2F;
        float num = (2.f*mu12 + C1F) * v1;
        float den = (musq + C1F) * v2;
        ssum += __fdividef(num, den);
    }

    __shared__ float red[256];
    red[tid] = ssum;
    __syncthreads();
    #pragma unroll
    for (int s = 128; s > 0; s >>= 1) {
        if (tid < s) red[tid] += red[tid + s];
        __syncthreads();
    }
    if (tid == 0) {
        atomicAdd(&g_acc[4 + n], (double)red[0]);
        __threadfence();
        unsigned int done = atomicAdd(&g_cnt, 1u);
        if (done == SSIM_BLOCKS - 1) {
            float psnr = 0.f, ssim = 0.f;
            #pragma unroll
            for (int k = 0; k < NB; k++) {
                float mse = (float)(g_acc[k] / (double)VOL);
                psnr += 10.0f * log10f(1.0f / mse);
                ssim += (float)(g_acc[4 + k] / (double)VOL);
            }
            if (out_size > 0) out[0] = psnr;
            if (out_size > 1) out[1] = ssim;
            if (out_size > 2) out[2] = (float)NB;
            for (int i = 3; i < out_size; i++) out[i] = 0.f;
            for (int i = 0; i < 8; i++) g_acc[i] = 0.0;  // restore invariant
            g_cnt = 0u;
        }
    }
}

extern "C" void kernel_launch(void* const* d_in, const int* in_sizes, int n_in,
                              void* d_out, int out_size) {
    const float* pred = (const float*)d_in[0];
    const float* gt   = (const float*)d_in[1];

    dim3 g1(WW/32, HH/32, NB*DD);
    blur2d_kernel<<<g1, 256>>>(pred, gt);

    dim3 g2(PLANE/256, NB);
    ssim_d_kernel<<<g2, 256>>>((float*)d_out, out_size);
}